// round 2
// baseline (speedup 1.0000x reference)
#include <cuda_runtime.h>
#include <math.h>

// ---------------- problem constants ----------------
#define BB   2
#define NQ   1220
#define ROWS (BB*NQ)        // 2440
#define DQ   512
#define DKV  256
#define H0   512
#define W0   512
#define HP   128
#define WP   128
#define HWP  (HP*WP)        // 16384
#define KT   512            // selected tokens
#define NH   8
#define HD   64
#define ZH   (BB*NH)        // 16 batch-heads

// ---------------- scratch (device globals; no allocs allowed) ----------------
__device__ float g_bev  [BB*DKV*HWP];     // pooled BEV  [b][c][hw]
__device__ float g_score[BB*HWP];
__device__ int   g_idx  [BB*KT];
__device__ float g_kvln [BB*KT*DKV];      // LN'd tokens
__device__ float g_k    [BB*KT*DQ];
__device__ float g_v    [BB*KT*DQ];
__device__ float g_aph  [ROWS*DQ];        // anchor-mlp hidden
__device__ float g_qin  [ROWS*DQ];        // query_input
__device__ float g_qln  [ROWS*DQ];
__device__ float g_q    [ROWS*DQ];
__device__ float g_gh   [ROWS*DQ];        // gate hidden
__device__ float g_gate [ROWS*DQ];
__device__ float g_S    [ZH*NQ*KT];       // attention logits/probs
__device__ float g_ctx  [ROWS*DQ];
__device__ float g_t1   [ROWS*DQ];
__device__ float g_t2   [ROWS*DQ];

// ---------------- 1) avg_pool2d 4x4 ----------------
__global__ void pool_kernel(const float* __restrict__ pts) {
    int i  = blockIdx.x * 256 + threadIdx.x;      // (b*256+c)*16384 + y*128 + x
    int x  = i & (WP - 1);
    int y  = (i >> 7) & (HP - 1);
    int bc = i >> 14;
    const float* p = pts + ((long)bc * H0 + y * 4) * (long)W0 + x * 4;
    float s = 0.f;
#pragma unroll
    for (int r = 0; r < 4; ++r) {
        float4 v = *(const float4*)(p + (long)r * W0);
        s += v.x + v.y + v.z + v.w;
    }
    g_bev[i] = s * 0.0625f;
}

// ---------------- 2) score = mean_c bev^2 ----------------
__global__ void score_kernel() {
    int i  = blockIdx.x * 256 + threadIdx.x;      // b*16384 + hw
    int b  = i >> 14;
    int hw = i & (HWP - 1);
    const float* bv = g_bev + (long)b * DKV * HWP + hw;
    float s = 0.f;
#pragma unroll 4
    for (int c = 0; c < DKV; ++c) {
        float v = bv[(long)c * HWP];
        s = fmaf(v, v, s);
    }
    g_score[i] = s * (1.f / DKV);
}

// ---------------- 3) deterministic top-K (radix select + prefix compaction) ----
__global__ void topk_kernel() {
    const int b   = blockIdx.x;
    const int tid = threadIdx.x;                  // 1024 threads, 16 elems each
    const float* sc = g_score + b * HWP;
    unsigned ub[16];
#pragma unroll
    for (int j = 0; j < 16; ++j) ub[j] = __float_as_uint(sc[tid * 16 + j]); // scores >= 0

    __shared__ int cnt;
    unsigned thr = 0u;
    for (int bit = 31; bit >= 0; --bit) {
        unsigned cand = thr | (1u << bit);
        if (tid == 0) cnt = 0;
        __syncthreads();
        int local = 0;
#pragma unroll
        for (int j = 0; j < 16; ++j) local += (ub[j] >= cand);
        for (int o = 16; o; o >>= 1) local += __shfl_xor_sync(0xffffffffu, local, o);
        if ((tid & 31) == 0) atomicAdd(&cnt, local);
        __syncthreads();
        if (cnt >= KT) thr = cand;                // all threads see same cnt
        __syncthreads();
    }
    // compact: strictly-greater first (deterministic order), then equals up to K
    __shared__ int sbuf[1024];
    __shared__ int tot;
    int c1 = 0;
#pragma unroll
    for (int j = 0; j < 16; ++j) c1 += (ub[j] > thr);
    sbuf[tid] = c1; __syncthreads();
    for (int off = 1; off < 1024; off <<= 1) {
        int v = (tid >= off) ? sbuf[tid - off] : 0;
        __syncthreads();
        sbuf[tid] += v;
        __syncthreads();
    }
    int start = sbuf[tid] - c1;
    if (tid == 1023) tot = sbuf[1023];
    __syncthreads();
    int m = tot;
#pragma unroll
    for (int j = 0; j < 16; ++j)
        if (ub[j] > thr) g_idx[b * KT + (start++)] = tid * 16 + j;
    __syncthreads();
    int c2 = 0;
#pragma unroll
    for (int j = 0; j < 16; ++j) c2 += (ub[j] == thr);
    sbuf[tid] = c2; __syncthreads();
    for (int off = 1; off < 1024; off <<= 1) {
        int v = (tid >= off) ? sbuf[tid - off] : 0;
        __syncthreads();
        sbuf[tid] += v;
        __syncthreads();
    }
    int s2 = m + sbuf[tid] - c2;
#pragma unroll
    for (int j = 0; j < 16; ++j)
        if (ub[j] == thr) { if (s2 < KT) g_idx[b * KT + s2] = tid * 16 + j; s2++; }
}

// ---------------- 4) gather tokens + bev_pos_mlp + LN(tn) ----------------
__global__ void token_kernel(const float* __restrict__ bw1, const float* __restrict__ bb1,
                             const float* __restrict__ bw2, const float* __restrict__ bb2,
                             const float* __restrict__ tnw, const float* __restrict__ tnb) {
    int bk = blockIdx.x;                          // b*512 + k
    int b  = bk >> 9;
    int id = g_idx[bk];
    int ys = id >> 7, xs = id & 127;
    float px = (xs + 0.5f) * (1.f / WP);
    float py = (ys + 0.5f) * (1.f / HP);
    int c = threadIdx.x;                          // 256 threads
    __shared__ float hid[DKV];
    hid[c] = fmaxf(fmaf(bw1[2 * c], px, fmaf(bw1[2 * c + 1], py, bb1[c])), 0.f);
    __syncthreads();
    float acc = bb2[c];
    const float* w2 = bw2 + (long)c * DKV;
#pragma unroll 8
    for (int j = 0; j < DKV; ++j) acc = fmaf(w2[j], hid[j], acc);
    float val = g_bev[((long)b * DKV + c) * HWP + id] + acc;

    // LayerNorm over 256 channels
    float s = val, sq = val * val;
    for (int o = 16; o; o >>= 1) {
        s  += __shfl_xor_sync(0xffffffffu, s, o);
        sq += __shfl_xor_sync(0xffffffffu, sq, o);
    }
    __shared__ float sa[8], sb[8];
    int w = c >> 5;
    if ((c & 31) == 0) { sa[w] = s; sb[w] = sq; }
    __syncthreads();
    s  = sa[0]+sa[1]+sa[2]+sa[3]+sa[4]+sa[5]+sa[6]+sa[7];
    sq = sb[0]+sb[1]+sb[2]+sb[3]+sb[4]+sb[5]+sb[6]+sb[7];
    float mean = s * (1.f / DKV);
    float var  = sq * (1.f / DKV) - mean * mean;
    float rs   = rsqrtf(var + 1e-5f);
    g_kvln[(long)bk * DKV + c] = (val - mean) * rs * tnw[c] + tnb[c];
}

// ---------------- 5) anchor pos-mlp hidden ----------------
__global__ void aph_kernel(const float* __restrict__ anc,
                           const float* __restrict__ aw1, const float* __restrict__ ab1) {
    int i = blockIdx.x * 256 + threadIdx.x;       // row*512 + c
    int row = i >> 9, c = i & 511;
    float ax = anc[row * 11 + 0], ay = anc[row * 11 + 1];
    float xr = fminf(fmaxf((ax + 51.2f) * (1.f / 102.4f), 0.f), 1.f);
    float yr = fminf(fmaxf((ay + 51.2f) * (1.f / 102.4f), 0.f), 1.f);
    g_aph[i] = fmaxf(fmaf(aw1[2 * c], xr, fmaf(aw1[2 * c + 1], yr, ab1[c])), 0.f);
}

// ---------------- generic register-blocked SGEMM (128x64 tile, 8x8 microtile) --
// C[M,N] = act(alpha * A @ op(B) + bias) (+ residual)
// TRANSB=1: B is [N,K] row-major (A@B^T). TRANSB=0: B is [K,N] row-major (A@B).
// 128 threads. Requires K % 16 == 0 (all our K are 64/256/512).
#define BM 128
#define BN 64
#define BK 16
template <int TRANSB>
__global__ void __launch_bounds__(128) gemm_kernel(
        const float* __restrict__ A, const float* __restrict__ Bm,
        const float* __restrict__ bias, const float* __restrict__ res,
        float* __restrict__ C,
        int M, int N, int Kd, int lda, int ldb, int ldc,
        int zMod, long aSB, long aSH, long bSB, long bSH,
        long cSB, long cSH,
        float alpha, int act, int hasBias, int hasRes) {
    int z  = blockIdx.z;
    int zb = z / zMod, zh = z % zMod;
    A  += zb * aSB + zh * aSH;
    Bm += zb * bSB + zh * bSH;
    long coff = zb * cSB + zh * cSH;

    const int tid = threadIdx.x;
    const int tx = tid & 7;               // 0..7  -> N
    const int ty = tid >> 3;              // 0..15 -> M
    const int i0 = blockIdx.x * BM, j0 = blockIdx.y * BN;

    __shared__ __align__(16) float As[BK][BM];
    __shared__ __align__(16) float Ws[BK][BN];
    float acc[8][8] = {};

    // A loader: thread tid owns global row i0+tid, all BK columns (4 x float4)
    const int arow = i0 + tid;
    // B loader (TRANSB=1): row (tid&63) of B-tile, 8 columns starting (tid>>6)*8
    const int tbrow = tid & 63;
    const int tbcol = (tid >> 6) * 8;
    // B loader (TRANSB=0): k-row tid>>3 (0..15), 8 columns (tid&7)*8
    const int nbk = tid >> 3;
    const int nbn = (tid & 7) * 8;

    for (int k0 = 0; k0 < Kd; k0 += BK) {
        // ---- load A tile (transposed into As[k][m]) ----
        if (arow < M) {
            const float* ap = A + (long)arow * lda + k0;
#pragma unroll
            for (int j = 0; j < 4; ++j) {
                float4 av = *(const float4*)(ap + j * 4);
                As[j * 4 + 0][tid] = av.x; As[j * 4 + 1][tid] = av.y;
                As[j * 4 + 2][tid] = av.z; As[j * 4 + 3][tid] = av.w;
            }
        } else {
#pragma unroll
            for (int j = 0; j < BK; ++j) As[j][tid] = 0.f;
        }
        // ---- load B tile into Ws[k][n] ----
        if (TRANSB) {
            float4 b0 = make_float4(0.f,0.f,0.f,0.f), b1 = b0;
            if (j0 + tbrow < N) {
                const float* bp = Bm + (long)(j0 + tbrow) * ldb + k0 + tbcol;
                b0 = *(const float4*)(bp);
                b1 = *(const float4*)(bp + 4);
            }
            Ws[tbcol + 0][tbrow] = b0.x; Ws[tbcol + 1][tbrow] = b0.y;
            Ws[tbcol + 2][tbrow] = b0.z; Ws[tbcol + 3][tbrow] = b0.w;
            Ws[tbcol + 4][tbrow] = b1.x; Ws[tbcol + 5][tbrow] = b1.y;
            Ws[tbcol + 6][tbrow] = b1.z; Ws[tbcol + 7][tbrow] = b1.w;
        } else {
            float4 b0 = make_float4(0.f,0.f,0.f,0.f), b1 = b0;
            if (j0 + nbn < N) {
                const float* bp = Bm + (long)(k0 + nbk) * ldb + j0 + nbn;
                b0 = *(const float4*)(bp);
                b1 = *(const float4*)(bp + 4);
            }
            *(float4*)&Ws[nbk][nbn]     = b0;
            *(float4*)&Ws[nbk][nbn + 4] = b1;
        }
        __syncthreads();
        // ---- compute 8x8 microtile ----
#pragma unroll
        for (int kk = 0; kk < BK; ++kk) {
            float a[8], b[8];
            *(float4*)&a[0] = *(const float4*)&As[kk][ty * 8];
            *(float4*)&a[4] = *(const float4*)&As[kk][ty * 8 + 4];
            *(float4*)&b[0] = *(const float4*)&Ws[kk][tx * 8];
            *(float4*)&b[4] = *(const float4*)&Ws[kk][tx * 8 + 4];
#pragma unroll
            for (int i = 0; i < 8; ++i)
#pragma unroll
                for (int j = 0; j < 8; ++j)
                    acc[i][j] = fmaf(a[i], b[j], acc[i][j]);
        }
        __syncthreads();
    }
    // ---- epilogue ----
#pragma unroll
    for (int i = 0; i < 8; ++i) {
        int row = i0 + ty * 8 + i;
        if (row >= M) continue;
#pragma unroll
        for (int j = 0; j < 8; ++j) {
            int col = j0 + tx * 8 + j;
            if (col >= N) continue;
            float v = alpha * acc[i][j];
            if (hasBias) v += bias[col];
            if (act == 1) v = fmaxf(v, 0.f);
            else if (act == 2) v = 1.f / (1.f + expf(-v));
            if (hasRes) v += res[coff + (long)row * ldc + col];
            C[coff + (long)row * ldc + col] = v;
        }
    }
}

// ---------------- LayerNorm over 512 ----------------
__global__ void ln512_kernel(const float* __restrict__ X, const float* __restrict__ w,
                             const float* __restrict__ bb, float* __restrict__ Y) {
    int row = blockIdx.x, t = threadIdx.x;        // 128 threads
    float4 v = *(const float4*)(X + (long)row * DQ + t * 4);
    float s  = v.x + v.y + v.z + v.w;
    float sq = v.x*v.x + v.y*v.y + v.z*v.z + v.w*v.w;
    for (int o = 16; o; o >>= 1) {
        s  += __shfl_xor_sync(0xffffffffu, s, o);
        sq += __shfl_xor_sync(0xffffffffu, sq, o);
    }
    __shared__ float sa[4], sb[4];
    int wp = t >> 5;
    if ((t & 31) == 0) { sa[wp] = s; sb[wp] = sq; }
    __syncthreads();
    s  = sa[0] + sa[1] + sa[2] + sa[3];
    sq = sb[0] + sb[1] + sb[2] + sb[3];
    float mean = s * (1.f / DQ);
    float var  = sq * (1.f / DQ) - mean * mean;
    float rs   = rsqrtf(var + 1e-5f);
    float4 wv = *(const float4*)(w  + t * 4);
    float4 bv = *(const float4*)(bb + t * 4);
    float4 o;
    o.x = (v.x - mean) * rs * wv.x + bv.x;
    o.y = (v.y - mean) * rs * wv.y + bv.y;
    o.z = (v.z - mean) * rs * wv.z + bv.z;
    o.w = (v.w - mean) * rs * wv.w + bv.w;
    *(float4*)(Y + (long)row * DQ + t * 4) = o;
}

// ---------------- softmax over 512 tokens ----------------
__global__ void softmax_kernel() {
    long row = blockIdx.x;                        // z*1220 + n
    float* s = g_S + row * KT;
    int t = threadIdx.x;                          // 128 threads
    float4 v = *(const float4*)(s + t * 4);
    float m = fmaxf(fmaxf(v.x, v.y), fmaxf(v.z, v.w));
    for (int o = 16; o; o >>= 1) m = fmaxf(m, __shfl_xor_sync(0xffffffffu, m, o));
    __shared__ float sm[4], ss[4];
    int wp = t >> 5;
    if ((t & 31) == 0) sm[wp] = m;
    __syncthreads();
    m = fmaxf(fmaxf(sm[0], sm[1]), fmaxf(sm[2], sm[3]));
    float4 e;
    e.x = expf(v.x - m); e.y = expf(v.y - m);
    e.z = expf(v.z - m); e.w = expf(v.w - m);
    float su = e.x + e.y + e.z + e.w;
    for (int o = 16; o; o >>= 1) su += __shfl_xor_sync(0xffffffffu, su, o);
    if ((t & 31) == 0) ss[wp] = su;
    __syncthreads();
    su = ss[0] + ss[1] + ss[2] + ss[3];
    float inv = 1.f / su;
    e.x *= inv; e.y *= inv; e.z *= inv; e.w *= inv;
    *(float4*)(s + t * 4) = e;
}

// ---------------- final: LN(on) + gated residual ----------------
__global__ void final_kernel(const float* __restrict__ inst, const float* __restrict__ onw,
                             const float* __restrict__ onb, float* __restrict__ out) {
    int row = blockIdx.x, t = threadIdx.x;        // 128 threads
    float4 v = *(const float4*)(g_t2 + (long)row * DQ + t * 4);
    float s  = v.x + v.y + v.z + v.w;
    float sq = v.x*v.x + v.y*v.y + v.z*v.z + v.w*v.w;
    for (int o = 16; o; o >>= 1) {
        s  += __shfl_xor_sync(0xffffffffu, s, o);
        sq += __shfl_xor_sync(0xffffffffu, sq, o);
    }
    __shared__ float sa[4], sb[4];
    int wp = t >> 5;
    if ((t & 31) == 0) { sa[wp] = s; sb[wp] = sq; }
    __syncthreads();
    s  = sa[0] + sa[1] + sa[2] + sa[3];
    sq = sb[0] + sb[1] + sb[2] + sb[3];
    float mean = s * (1.f / DQ);
    float var  = sq * (1.f / DQ) - mean * mean;
    float rs   = rsqrtf(var + 1e-5f);
    float4 wv = *(const float4*)(onw + t * 4);
    float4 bv = *(const float4*)(onb + t * 4);
    float4 g  = *(const float4*)(g_gate + (long)row * DQ + t * 4);
    float4 in = *(const float4*)(inst   + (long)row * DQ + t * 4);
    float4 o;
    o.x = in.x + g.x * ((v.x - mean) * rs * wv.x + bv.x);
    o.y = in.y + g.y * ((v.y - mean) * rs * wv.y + bv.y);
    o.z = in.z + g.z * ((v.z - mean) * rs * wv.z + bv.z);
    o.w = in.w + g.w * ((v.w - mean) * rs * wv.w + bv.w);
    *(float4*)(out + (long)row * DQ + t * 4) = o;
}

// ---------------- host side ----------------
static inline void launch_gemm(int transb,
    const float* A, const float* Bm, const float* bias, const float* res, float* C,
    int M, int N, int Kd, int lda, int ldb, int ldc,
    int Z, int zMod, long aSB, long aSH, long bSB, long bSH, long cSB, long cSH,
    float alpha, int act, int hb, int hr) {
    dim3 grid((M + BM - 1) / BM, (N + BN - 1) / BN, Z);
    if (transb)
        gemm_kernel<1><<<grid, 128>>>(A, Bm, bias, res, C, M, N, Kd, lda, ldb, ldc,
                                      zMod, aSB, aSH, bSB, bSH, cSB, cSH, alpha, act, hb, hr);
    else
        gemm_kernel<0><<<grid, 128>>>(A, Bm, bias, res, C, M, N, Kd, lda, ldb, ldc,
                                      zMod, aSB, aSH, bSB, bSH, cSB, cSH, alpha, act, hb, hr);
}

extern "C" void kernel_launch(void* const* d_in, const int* in_sizes, int n_in,
                              void* d_out, int out_size) {
    const float* inst = (const float*)d_in[0];
    const float* pts  = (const float*)d_in[1];
    const float* anc  = (const float*)d_in[2];
    const float* qw   = (const float*)d_in[3];
    const float* qb   = (const float*)d_in[4];
    const float* kw   = (const float*)d_in[5];
    const float* kb   = (const float*)d_in[6];
    const float* vw   = (const float*)d_in[7];
    const float* vb   = (const float*)d_in[8];
    const float* aow  = (const float*)d_in[9];
    const float* aob  = (const float*)d_in[10];
    const float* qnw  = (const float*)d_in[11];
    const float* qnb  = (const float*)d_in[12];
    const float* tnw  = (const float*)d_in[13];
    const float* tnb  = (const float*)d_in[14];
    const float* onw  = (const float*)d_in[15];
    const float* onb  = (const float*)d_in[16];
    const float* opw  = (const float*)d_in[17];
    const float* opb  = (const float*)d_in[18];
    const float* bw1  = (const float*)d_in[19];
    const float* bb1  = (const float*)d_in[20];
    const float* bw2  = (const float*)d_in[21];
    const float* bb2  = (const float*)d_in[22];
    const float* aw1  = (const float*)d_in[23];
    const float* ab1  = (const float*)d_in[24];
    const float* aw2  = (const float*)d_in[25];
    const float* ab2  = (const float*)d_in[26];
    const float* gw1  = (const float*)d_in[27];
    const float* gb1  = (const float*)d_in[28];
    const float* gw2  = (const float*)d_in[29];
    const float* gb2  = (const float*)d_in[30];
    float* out = (float*)d_out;

    void* p;
    cudaGetSymbolAddress(&p, g_aph);  float* p_aph  = (float*)p;
    cudaGetSymbolAddress(&p, g_qin);  float* p_qin  = (float*)p;
    cudaGetSymbolAddress(&p, g_qln);  float* p_qln  = (float*)p;
    cudaGetSymbolAddress(&p, g_q);    float* p_q    = (float*)p;
    cudaGetSymbolAddress(&p, g_gh);   float* p_gh   = (float*)p;
    cudaGetSymbolAddress(&p, g_gate); float* p_gate = (float*)p;
    cudaGetSymbolAddress(&p, g_kvln); float* p_kvln = (float*)p;
    cudaGetSymbolAddress(&p, g_k);    float* p_k    = (float*)p;
    cudaGetSymbolAddress(&p, g_v);    float* p_v    = (float*)p;
    cudaGetSymbolAddress(&p, g_S);    float* p_S    = (float*)p;
    cudaGetSymbolAddress(&p, g_ctx);  float* p_ctx  = (float*)p;
    cudaGetSymbolAddress(&p, g_t1);   float* p_t1   = (float*)p;
    cudaGetSymbolAddress(&p, g_t2);   float* p_t2   = (float*)p;

    // BEV pipeline
    pool_kernel <<<(BB * DKV * HWP) / 256, 256>>>(pts);
    score_kernel<<<(BB * HWP) / 256, 256>>>();
    topk_kernel <<<BB, 1024>>>();
    token_kernel<<<BB * KT, 256>>>(bw1, bb1, bw2, bb2, tnw, tnb);

    // query path
    aph_kernel<<<(ROWS * DQ) / 256, 256>>>(anc, aw1, ab1);
    // qin = aph @ ap_w2^T + ap_b2 + instance
    launch_gemm(1, p_aph, aw2, ab2, inst, p_qin, ROWS, DQ, DQ, DQ, DQ, DQ,
                1, 1, 0, 0, 0, 0, 0, 0, 1.f, 0, 1, 1);
    ln512_kernel<<<ROWS, 128>>>(p_qin, qnw, qnb, p_qln);
    // q = qln @ qw^T + qb
    launch_gemm(1, p_qln, qw, qb, nullptr, p_q, ROWS, DQ, DQ, DQ, DQ, DQ,
                1, 1, 0, 0, 0, 0, 0, 0, 1.f, 0, 1, 0);
    // gate hidden = relu(qin @ g_w1^T + g_b1)
    launch_gemm(1, p_qin, gw1, gb1, nullptr, p_gh, ROWS, DQ, DQ, DQ, DQ, DQ,
                1, 1, 0, 0, 0, 0, 0, 0, 1.f, 1, 1, 0);
    // gate = sigmoid(gh @ g_w2^T + g_b2)
    launch_gemm(1, p_gh, gw2, gb2, nullptr, p_gate, ROWS, DQ, DQ, DQ, DQ, DQ,
                1, 1, 0, 0, 0, 0, 0, 0, 1.f, 2, 1, 0);

    // k/v projections: [B*K, 256] @ [512,256]^T
    launch_gemm(1, p_kvln, kw, kb, nullptr, p_k, BB * KT, DQ, DKV, DKV, DKV, DQ,
                1, 1, 0, 0, 0, 0, 0, 0, 1.f, 0, 1, 0);
    launch_gemm(1, p_kvln, vw, vb, nullptr, p_v, BB * KT, DQ, DKV, DKV, DKV, DQ,
                1, 1, 0, 0, 0, 0, 0, 0, 1.f, 0, 1, 0);

    // S[b,h] = 0.125 * q_h @ k_h^T   (16 batch-heads)
    launch_gemm(1, p_q, p_k, nullptr, nullptr, p_S, NQ, KT, HD, DQ, DQ, KT,
                ZH, NH,
                (long)NQ * DQ, (long)HD,          // A strides (batch, head)
                (long)KT * DQ, (long)HD,          // B strides
                (long)NH * NQ * KT, (long)NQ * KT,// C strides
                0.125f, 0, 0, 0);
    softmax_kernel<<<ZH * NQ, 128>>>();
    // ctx[b, n, h*64+d] = P @ V
    launch_gemm(0, p_S, p_v, nullptr, nullptr, p_ctx, NQ, HD, KT, KT, DQ, DQ,
                ZH, NH,
                (long)NH * NQ * KT, (long)NQ * KT,
                (long)KT * DQ, (long)HD,
                (long)NQ * DQ, (long)HD,
                1.f, 0, 0, 0);

    // out projections
    launch_gemm(1, p_ctx, aow, aob, nullptr, p_t1, ROWS, DQ, DQ, DQ, DQ, DQ,
                1, 1, 0, 0, 0, 0, 0, 0, 1.f, 0, 1, 0);
    launch_gemm(1, p_t1, opw, opb, nullptr, p_t2, ROWS, DQ, DQ, DQ, DQ, DQ,
                1, 1, 0, 0, 0, 0, 0, 0, 1.f, 0, 1, 0);

    // LN(on) + gated residual
    final_kernel<<<ROWS, 128>>>(inst, onw, onb, out);
}

// round 6
// speedup vs baseline: 1.5543x; 1.5543x over previous
#include <cuda_runtime.h>
#include <math.h>

// ---------------- problem constants ----------------
#define BB   2
#define NQ   1220
#define ROWS (BB*NQ)        // 2440
#define DQ   512
#define DKV  256
#define H0   512
#define W0   512
#define HP   128
#define WP   128
#define HWP  (HP*WP)        // 16384
#define KT   512            // selected tokens
#define NH   8
#define HD   64
#define ZH   (BB*NH)        // 16 batch-heads

// ---------------- scratch (device globals; no allocs allowed) ----------------
__device__ float g_bev  [BB*DKV*HWP];     // pooled BEV  [b][c][hw]
__device__ float g_score[BB*HWP];
__device__ int   g_idx  [BB*KT];
__device__ float g_hid  [BB*KT*DKV];      // token pos-mlp hidden
__device__ float g_tokm [BB*KT*DKV];      // token pos-mlp out
__device__ float g_kvln [BB*KT*DKV];      // LN'd tokens
__device__ float g_k    [BB*KT*DQ];
__device__ float g_v    [BB*KT*DQ];
__device__ float g_aph  [ROWS*DQ];        // anchor-mlp hidden
__device__ float g_qin  [ROWS*DQ];        // query_input
__device__ float g_qln  [ROWS*DQ];
__device__ float g_q    [ROWS*DQ];
__device__ float g_gh   [ROWS*DQ];        // gate hidden
__device__ float g_gate [ROWS*DQ];
__device__ float g_S    [ZH*NQ*KT];       // attention logits/probs
__device__ float g_ctx  [ROWS*DQ];
__device__ float g_t1   [ROWS*DQ];
__device__ float g_t2   [ROWS*DQ];

// ---------------- 1) avg_pool2d 4x4 ----------------
__global__ void pool_kernel(const float* __restrict__ pts) {
    int i  = blockIdx.x * 256 + threadIdx.x;      // (b*256+c)*16384 + y*128 + x
    int x  = i & (WP - 1);
    int y  = (i >> 7) & (HP - 1);
    int bc = i >> 14;
    const float* p = pts + ((long)bc * H0 + y * 4) * (long)W0 + x * 4;
    float s = 0.f;
#pragma unroll
    for (int r = 0; r < 4; ++r) {
        float4 v = *(const float4*)(p + (long)r * W0);
        s += v.x + v.y + v.z + v.w;
    }
    g_bev[i] = s * 0.0625f;
}

// ---------------- 2) score = mean_c bev^2 ----------------
__global__ void score_kernel() {
    int i  = blockIdx.x * 256 + threadIdx.x;      // b*16384 + hw
    int b  = i >> 14;
    int hw = i & (HWP - 1);
    const float* bv = g_bev + (long)b * DKV * HWP + hw;
    float s = 0.f;
#pragma unroll 4
    for (int c = 0; c < DKV; ++c) {
        float v = bv[(long)c * HWP];
        s = fmaf(v, v, s);
    }
    g_score[i] = s * (1.f / DKV);
}

// ---------------- 3) deterministic top-K (radix select + prefix compaction) ----
__global__ void topk_kernel() {
    const int b   = blockIdx.x;
    const int tid = threadIdx.x;                  // 1024 threads, 16 elems each
    const float* sc = g_score + b * HWP;
    unsigned ub[16];
#pragma unroll
    for (int j = 0; j < 16; ++j) ub[j] = __float_as_uint(sc[tid * 16 + j]); // scores >= 0

    __shared__ int cnt;
    unsigned thr = 0u;
    for (int bit = 31; bit >= 0; --bit) {
        unsigned cand = thr | (1u << bit);
        if (tid == 0) cnt = 0;
        __syncthreads();
        int local = 0;
#pragma unroll
        for (int j = 0; j < 16; ++j) local += (ub[j] >= cand);
        for (int o = 16; o; o >>= 1) local += __shfl_xor_sync(0xffffffffu, local, o);
        if ((tid & 31) == 0) atomicAdd(&cnt, local);
        __syncthreads();
        if (cnt >= KT) thr = cand;                // all threads see same cnt
        __syncthreads();
    }
    // compact: strictly-greater first (deterministic order), then equals up to K
    __shared__ int sbuf[1024];
    __shared__ int tot;
    int c1 = 0;
#pragma unroll
    for (int j = 0; j < 16; ++j) c1 += (ub[j] > thr);
    sbuf[tid] = c1; __syncthreads();
    for (int off = 1; off < 1024; off <<= 1) {
        int v = (tid >= off) ? sbuf[tid - off] : 0;
        __syncthreads();
        sbuf[tid] += v;
        __syncthreads();
    }
    int start = sbuf[tid] - c1;
    if (tid == 1023) tot = sbuf[1023];
    __syncthreads();
    int m = tot;
#pragma unroll
    for (int j = 0; j < 16; ++j)
        if (ub[j] > thr) g_idx[b * KT + (start++)] = tid * 16 + j;
    __syncthreads();
    int c2 = 0;
#pragma unroll
    for (int j = 0; j < 16; ++j) c2 += (ub[j] == thr);
    sbuf[tid] = c2; __syncthreads();
    for (int off = 1; off < 1024; off <<= 1) {
        int v = (tid >= off) ? sbuf[tid - off] : 0;
        __syncthreads();
        sbuf[tid] += v;
        __syncthreads();
    }
    int s2 = m + sbuf[tid] - c2;
#pragma unroll
    for (int j = 0; j < 16; ++j)
        if (ub[j] == thr) { if (s2 < KT) g_idx[b * KT + s2] = tid * 16 + j; s2++; }
}

// ---------------- 4a) per-token pos-mlp hidden ----------------
__global__ void tokhid_kernel(const float* __restrict__ bw1, const float* __restrict__ bb1) {
    int bk = blockIdx.x;                          // b*512 + k
    int c  = threadIdx.x;                         // 256 threads
    int id = g_idx[bk];
    float px = ((id & 127) + 0.5f) * (1.f / WP);
    float py = ((id >> 7)  + 0.5f) * (1.f / HP);
    g_hid[bk * DKV + c] =
        fmaxf(fmaf(bw1[2 * c], px, fmaf(bw1[2 * c + 1], py, bb1[c])), 0.f);
}

// ---------------- 4b) gather + add mlp-out + LN(tn) ----------------
__global__ void gatherln_kernel(const float* __restrict__ tnw, const float* __restrict__ tnb) {
    int bk = blockIdx.x;                          // b*512 + k
    int b  = bk >> 9;
    int id = g_idx[bk];
    int c  = threadIdx.x;                         // 256 threads
    float val = g_bev[((long)b * DKV + c) * HWP + id] + g_tokm[(long)bk * DKV + c];

    float s = val, sq = val * val;
    for (int o = 16; o; o >>= 1) {
        s  += __shfl_xor_sync(0xffffffffu, s, o);
        sq += __shfl_xor_sync(0xffffffffu, sq, o);
    }
    __shared__ float sa[8], sb[8];
    int w = c >> 5;
    if ((c & 31) == 0) { sa[w] = s; sb[w] = sq; }
    __syncthreads();
    s  = sa[0]+sa[1]+sa[2]+sa[3]+sa[4]+sa[5]+sa[6]+sa[7];
    sq = sb[0]+sb[1]+sb[2]+sb[3]+sb[4]+sb[5]+sb[6]+sb[7];
    float mean = s * (1.f / DKV);
    float var  = sq * (1.f / DKV) - mean * mean;
    float rs   = rsqrtf(var + 1e-5f);
    g_kvln[(long)bk * DKV + c] = (val - mean) * rs * tnw[c] + tnb[c];
}

// ---------------- 5) anchor pos-mlp hidden ----------------
__global__ void aph_kernel(const float* __restrict__ anc,
                           const float* __restrict__ aw1, const float* __restrict__ ab1) {
    int i = blockIdx.x * 256 + threadIdx.x;       // row*512 + c
    int row = i >> 9, c = i & 511;
    float ax = anc[row * 11 + 0], ay = anc[row * 11 + 1];
    float xr = fminf(fmaxf((ax + 51.2f) * (1.f / 102.4f), 0.f), 1.f);
    float yr = fminf(fmaxf((ay + 51.2f) * (1.f / 102.4f), 0.f), 1.f);
    g_aph[i] = fmaxf(fmaf(aw1[2 * c], xr, fmaf(aw1[2 * c + 1], yr, ab1[c])), 0.f);
}

// ---------------- SGEMM v2: 128x64x16 tile, 256 threads, 8x4 micro, dbl-buffered
// C[M,N] = act(alpha * A @ op(B) + bias) (+ residual)
// TRANSB=1: B is [N,K] row-major (A@B^T). TRANSB=0: B is [K,N] row-major (A@B).
// Requires N % 64 == 0 and K % 16 == 0 (true for all call sites).
#define BM 128
#define BN 64
#define BK 16
template <int TRANSB>
__global__ void __launch_bounds__(256) gemm_kernel(
        const float* __restrict__ A, const float* __restrict__ Bm,
        const float* __restrict__ bias, const float* __restrict__ res,
        float* __restrict__ C,
        int M, int N, int Kd, int lda, int ldb, int ldc,
        int zMod, long aSB, long aSH, long bSB, long bSH,
        long cSB, long cSH,
        float alpha, int act, int hasBias, int hasRes) {
    int z  = blockIdx.z;
    int zb = z / zMod, zh = z % zMod;
    A  += zb * aSB + zh * aSH;
    Bm += zb * bSB + zh * bSH;
    long coff = zb * cSB + zh * cSH;

    const int tid = threadIdx.x;
    const int ty = tid >> 4;              // 0..15 -> 8 M-rows each
    const int tx = tid & 15;              // 0..15 -> 4 N-cols each
    const int i0 = blockIdx.x * BM, j0 = blockIdx.y * BN;

    __shared__ __align__(16) float As[BK][BM];
    __shared__ __align__(16) float Ws[BK][BN];
    float acc[8][4] = {};

    // A loader: row tid>>1 (0..127), 8 k-cols starting (tid&1)*8
    const int ar = tid >> 1;
    const int ac = (tid & 1) * 8;
    // B loader TRANSB=1: n-row tid>>2 (0..63), 4 k-cols (tid&3)*4
    const int tbr = tid >> 2;
    const int tbc = (tid & 3) * 4;
    // B loader TRANSB=0: k-row tid>>4 (0..15), 4 n-cols (tid&15)*4
    const int nbr = tid >> 4;
    const int nbc = (tid & 15) * 4;

    float4 ra0, ra1, rb;

    // ---- prologue: load tile 0 ----
    {
        if (i0 + ar < M) {
            const float* ap = A + (long)(i0 + ar) * lda + ac;
            ra0 = *(const float4*)ap; ra1 = *(const float4*)(ap + 4);
        } else { ra0 = make_float4(0,0,0,0); ra1 = ra0; }
        if (TRANSB) rb = *(const float4*)(Bm + (long)(j0 + tbr) * ldb + tbc);
        else        rb = *(const float4*)(Bm + (long)nbr * ldb + j0 + nbc);
        As[ac+0][ar]=ra0.x; As[ac+1][ar]=ra0.y; As[ac+2][ar]=ra0.z; As[ac+3][ar]=ra0.w;
        As[ac+4][ar]=ra1.x; As[ac+5][ar]=ra1.y; As[ac+6][ar]=ra1.z; As[ac+7][ar]=ra1.w;
        if (TRANSB) {
            Ws[tbc+0][tbr]=rb.x; Ws[tbc+1][tbr]=rb.y;
            Ws[tbc+2][tbr]=rb.z; Ws[tbc+3][tbr]=rb.w;
        } else {
            *(float4*)&Ws[nbr][nbc] = rb;
        }
    }
    __syncthreads();

    for (int k0 = 0;;) {
        int kn = k0 + BK;
        bool more = kn < Kd;
        // ---- prefetch next tile into regs (latency hidden by compute) ----
        if (more) {
            if (i0 + ar < M) {
                const float* ap = A + (long)(i0 + ar) * lda + kn + ac;
                ra0 = *(const float4*)ap; ra1 = *(const float4*)(ap + 4);
            } else { ra0 = make_float4(0,0,0,0); ra1 = ra0; }
            if (TRANSB) rb = *(const float4*)(Bm + (long)(j0 + tbr) * ldb + kn + tbc);
            else        rb = *(const float4*)(Bm + (long)(kn + nbr) * ldb + j0 + nbc);
        }
        // ---- compute ----
#pragma unroll
        for (int kk = 0; kk < BK; ++kk) {
            float a[8], b[4];
            *(float4*)&a[0] = *(const float4*)&As[kk][ty * 8];
            *(float4*)&a[4] = *(const float4*)&As[kk][ty * 8 + 4];
            *(float4*)&b[0] = *(const float4*)&Ws[kk][tx * 4];
#pragma unroll
            for (int i = 0; i < 8; ++i)
#pragma unroll
                for (int j = 0; j < 4; ++j)
                    acc[i][j] = fmaf(a[i], b[j], acc[i][j]);
        }
        __syncthreads();
        if (!more) break;
        // ---- store prefetched regs to smem ----
        As[ac+0][ar]=ra0.x; As[ac+1][ar]=ra0.y; As[ac+2][ar]=ra0.z; As[ac+3][ar]=ra0.w;
        As[ac+4][ar]=ra1.x; As[ac+5][ar]=ra1.y; As[ac+6][ar]=ra1.z; As[ac+7][ar]=ra1.w;
        if (TRANSB) {
            Ws[tbc+0][tbr]=rb.x; Ws[tbc+1][tbr]=rb.y;
            Ws[tbc+2][tbr]=rb.z; Ws[tbc+3][tbr]=rb.w;
        } else {
            *(float4*)&Ws[nbr][nbc] = rb;
        }
        __syncthreads();
        k0 = kn;
    }

    // ---- epilogue ----
#pragma unroll
    for (int i = 0; i < 8; ++i) {
        int row = i0 + ty * 8 + i;
        if (row >= M) continue;
        int col = j0 + tx * 4;
        float4 v;
        float vv[4];
#pragma unroll
        for (int j = 0; j < 4; ++j) {
            float x = alpha * acc[i][j];
            if (hasBias) x += bias[col + j];
            if (act == 1) x = fmaxf(x, 0.f);
            else if (act == 2) x = 1.f / (1.f + expf(-x));
            vv[j] = x;
        }
        if (hasRes) {
            float4 r = *(const float4*)(res + coff + (long)row * ldc + col);
            vv[0] += r.x; vv[1] += r.y; vv[2] += r.z; vv[3] += r.w;
        }
        v.x = vv[0]; v.y = vv[1]; v.z = vv[2]; v.w = vv[3];
        *(float4*)(C + coff + (long)row * ldc + col) = v;
    }
}

// ---------------- LayerNorm over 512 ----------------
__global__ void ln512_kernel(const float* __restrict__ X, const float* __restrict__ w,
                             const float* __restrict__ bb, float* __restrict__ Y) {
    int row = blockIdx.x, t = threadIdx.x;        // 128 threads
    float4 v = *(const float4*)(X + (long)row * DQ + t * 4);
    float s  = v.x + v.y + v.z + v.w;
    float sq = v.x*v.x + v.y*v.y + v.z*v.z + v.w*v.w;
    for (int o = 16; o; o >>= 1) {
        s  += __shfl_xor_sync(0xffffffffu, s, o);
        sq += __shfl_xor_sync(0xffffffffu, sq, o);
    }
    __shared__ float sa[4], sb[4];
    int wp = t >> 5;
    if ((t & 31) == 0) { sa[wp] = s; sb[wp] = sq; }
    __syncthreads();
    s  = sa[0] + sa[1] + sa[2] + sa[3];
    sq = sb[0] + sb[1] + sb[2] + sb[3];
    float mean = s * (1.f / DQ);
    float var  = sq * (1.f / DQ) - mean * mean;
    float rs   = rsqrtf(var + 1e-5f);
    float4 wv = *(const float4*)(w  + t * 4);
    float4 bv = *(const float4*)(bb + t * 4);
    float4 o;
    o.x = (v.x - mean) * rs * wv.x + bv.x;
    o.y = (v.y - mean) * rs * wv.y + bv.y;
    o.z = (v.z - mean) * rs * wv.z + bv.z;
    o.w = (v.w - mean) * rs * wv.w + bv.w;
    *(float4*)(Y + (long)row * DQ + t * 4) = o;
}

// ---------------- softmax over 512 tokens ----------------
__global__ void softmax_kernel() {
    long row = blockIdx.x;                        // z*1220 + n
    float* s = g_S + row * KT;
    int t = threadIdx.x;                          // 128 threads
    float4 v = *(const float4*)(s + t * 4);
    float m = fmaxf(fmaxf(v.x, v.y), fmaxf(v.z, v.w));
    for (int o = 16; o; o >>= 1) m = fmaxf(m, __shfl_xor_sync(0xffffffffu, m, o));
    __shared__ float sm[4], ss[4];
    int wp = t >> 5;
    if ((t & 31) == 0) sm[wp] = m;
    __syncthreads();
    m = fmaxf(fmaxf(sm[0], sm[1]), fmaxf(sm[2], sm[3]));
    float4 e;
    e.x = expf(v.x - m); e.y = expf(v.y - m);
    e.z = expf(v.z - m); e.w = expf(v.w - m);
    float su = e.x + e.y + e.z + e.w;
    for (int o = 16; o; o >>= 1) su += __shfl_xor_sync(0xffffffffu, su, o);
    if ((t & 31) == 0) ss[wp] = su;
    __syncthreads();
    su = ss[0] + ss[1] + ss[2] + ss[3];
    float inv = 1.f / su;
    e.x *= inv; e.y *= inv; e.z *= inv; e.w *= inv;
    *(float4*)(s + t * 4) = e;
}

// ---------------- final: LN(on) + gated residual ----------------
__global__ void final_kernel(const float* __restrict__ inst, const float* __restrict__ onw,
                             const float* __restrict__ onb, float* __restrict__ out) {
    int row = blockIdx.x, t = threadIdx.x;        // 128 threads
    float4 v = *(const float4*)(g_t2 + (long)row * DQ + t * 4);
    float s  = v.x + v.y + v.z + v.w;
    float sq = v.x*v.x + v.y*v.y + v.z*v.z + v.w*v.w;
    for (int o = 16; o; o >>= 1) {
        s  += __shfl_xor_sync(0xffffffffu, s, o);
        sq += __shfl_xor_sync(0xffffffffu, sq, o);
    }
    __shared__ float sa[4], sb[4];
    int wp = t >> 5;
    if ((t & 31) == 0) { sa[wp] = s; sb[wp] = sq; }
    __syncthreads();
    s  = sa[0] + sa[1] + sa[2] + sa[3];
    sq = sb[0] + sb[1] + sb[2] + sb[3];
    float mean = s * (1.f / DQ);
    float var  = sq * (1.f / DQ) - mean * mean;
    float rs   = rsqrtf(var + 1e-5f);
    float4 wv = *(const float4*)(onw + t * 4);
    float4 bv = *(const float4*)(onb + t * 4);
    float4 g  = *(const float4*)(g_gate + (long)row * DQ + t * 4);
    float4 in = *(const float4*)(inst   + (long)row * DQ + t * 4);
    float4 o;
    o.x = in.x + g.x * ((v.x - mean) * rs * wv.x + bv.x);
    o.y = in.y + g.y * ((v.y - mean) * rs * wv.y + bv.y);
    o.z = in.z + g.z * ((v.z - mean) * rs * wv.z + bv.z);
    o.w = in.w + g.w * ((v.w - mean) * rs * wv.w + bv.w);
    *(float4*)(out + (long)row * DQ + t * 4) = o;
}

// ---------------- host side ----------------
static inline void launch_gemm(int transb,
    const float* A, const float* Bm, const float* bias, const float* res, float* C,
    int M, int N, int Kd, int lda, int ldb, int ldc,
    int Z, int zMod, long aSB, long aSH, long bSB, long bSH, long cSB, long cSH,
    float alpha, int act, int hb, int hr) {
    dim3 grid((M + BM - 1) / BM, (N + BN - 1) / BN, Z);
    if (transb)
        gemm_kernel<1><<<grid, 256>>>(A, Bm, bias, res, C, M, N, Kd, lda, ldb, ldc,
                                      zMod, aSB, aSH, bSB, bSH, cSB, cSH, alpha, act, hb, hr);
    else
        gemm_kernel<0><<<grid, 256>>>(A, Bm, bias, res, C, M, N, Kd, lda, ldb, ldc,
                                      zMod, aSB, aSH, bSB, bSH, cSB, cSH, alpha, act, hb, hr);
}

extern "C" void kernel_launch(void* const* d_in, const int* in_sizes, int n_in,
                              void* d_out, int out_size) {
    const float* inst = (const float*)d_in[0];
    const float* pts  = (const float*)d_in[1];
    const float* anc  = (const float*)d_in[2];
    const float* qw   = (const float*)d_in[3];
    const float* qb   = (const float*)d_in[4];
    const float* kw   = (const float*)d_in[5];
    const float* kb   = (const float*)d_in[6];
    const float* vw   = (const float*)d_in[7];
    const float* vb   = (const float*)d_in[8];
    const float* aow  = (const float*)d_in[9];
    const float* aob  = (const float*)d_in[10];
    const float* qnw  = (const float*)d_in[11];
    const float* qnb  = (const float*)d_in[12];
    const float* tnw  = (const float*)d_in[13];
    const float* tnb  = (const float*)d_in[14];
    const float* onw  = (const float*)d_in[15];
    const float* onb  = (const float*)d_in[16];
    const float* opw  = (const float*)d_in[17];
    const float* opb  = (const float*)d_in[18];
    const float* bw1  = (const float*)d_in[19];
    const float* bb1  = (const float*)d_in[20];
    const float* bw2  = (const float*)d_in[21];
    const float* bb2  = (const float*)d_in[22];
    const float* aw1  = (const float*)d_in[23];
    const float* ab1  = (const float*)d_in[24];
    const float* aw2  = (const float*)d_in[25];
    const float* ab2  = (const float*)d_in[26];
    const float* gw1  = (const float*)d_in[27];
    const float* gb1  = (const float*)d_in[28];
    const float* gw2  = (const float*)d_in[29];
    const float* gb2  = (const float*)d_in[30];
    float* out = (float*)d_out;

    void* p;
    cudaGetSymbolAddress(&p, g_hid);  float* p_hid  = (float*)p;
    cudaGetSymbolAddress(&p, g_tokm); float* p_tokm = (float*)p;
    cudaGetSymbolAddress(&p, g_aph);  float* p_aph  = (float*)p;
    cudaGetSymbolAddress(&p, g_qin);  float* p_qin  = (float*)p;
    cudaGetSymbolAddress(&p, g_qln);  float* p_qln  = (float*)p;
    cudaGetSymbolAddress(&p, g_q);    float* p_q    = (float*)p;
    cudaGetSymbolAddress(&p, g_gh);   float* p_gh   = (float*)p;
    cudaGetSymbolAddress(&p, g_gate); float* p_gate = (float*)p;
    cudaGetSymbolAddress(&p, g_kvln); float* p_kvln = (float*)p;
    cudaGetSymbolAddress(&p, g_k);    float* p_k    = (float*)p;
    cudaGetSymbolAddress(&p, g_v);    float* p_v    = (float*)p;
    cudaGetSymbolAddress(&p, g_S);    float* p_S    = (float*)p;
    cudaGetSymbolAddress(&p, g_ctx);  float* p_ctx  = (float*)p;
    cudaGetSymbolAddress(&p, g_t1);   float* p_t1   = (float*)p;
    cudaGetSymbolAddress(&p, g_t2);   float* p_t2   = (float*)p;

    // BEV pipeline
    pool_kernel <<<(BB * DKV * HWP) / 256, 256>>>(pts);
    score_kernel<<<(BB * HWP) / 256, 256>>>();
    topk_kernel <<<BB, 1024>>>();
    tokhid_kernel<<<BB * KT, 256>>>(bw1, bb1);
    // tokm = hid @ bw2^T + bb2   [1024 x 256]
    launch_gemm(1, p_hid, bw2, bb2, nullptr, p_tokm, BB * KT, DKV, DKV, DKV, DKV, DKV,
                1, 1, 0, 0, 0, 0, 0, 0, 1.f, 0, 1, 0);
    gatherln_kernel<<<BB * KT, 256>>>(tnw, tnb);

    // query path
    aph_kernel<<<(ROWS * DQ) / 256, 256>>>(anc, aw1, ab1);
    // qin = aph @ ap_w2^T + ap_b2 + instance
    launch_gemm(1, p_aph, aw2, ab2, inst, p_qin, ROWS, DQ, DQ, DQ, DQ, DQ,
                1, 1, 0, 0, 0, 0, 0, 0, 1.f, 0, 1, 1);
    ln512_kernel<<<ROWS, 128>>>(p_qin, qnw, qnb, p_qln);
    // q = qln @ qw^T + qb
    launch_gemm(1, p_qln, qw, qb, nullptr, p_q, ROWS, DQ, DQ, DQ, DQ, DQ,
                1, 1, 0, 0, 0, 0, 0, 0, 1.f, 0, 1, 0);
    // gate hidden = relu(qin @ g_w1^T + g_b1)
    launch_gemm(1, p_qin, gw1, gb1, nullptr, p_gh, ROWS, DQ, DQ, DQ, DQ, DQ,
                1, 1, 0, 0, 0, 0, 0, 0, 1.f, 1, 1, 0);
    // gate = sigmoid(gh @ g_w2^T + g_b2)
    launch_gemm(1, p_gh, gw2, gb2, nullptr, p_gate, ROWS, DQ, DQ, DQ, DQ, DQ,
                1, 1, 0, 0, 0, 0, 0, 0, 1.f, 2, 1, 0);

    // k/v projections: [B*K, 256] @ [512,256]^T
    launch_gemm(1, p_kvln, kw, kb, nullptr, p_k, BB * KT, DQ, DKV, DKV, DKV, DQ,
                1, 1, 0, 0, 0, 0, 0, 0, 1.f, 0, 1, 0);
    launch_gemm(1, p_kvln, vw, vb, nullptr, p_v, BB * KT, DQ, DKV, DKV, DKV, DQ,
                1, 1, 0, 0, 0, 0, 0, 0, 1.f, 0, 1, 0);

    // S[b,h] = 0.125 * q_h @ k_h^T   (16 batch-heads)
    launch_gemm(1, p_q, p_k, nullptr, nullptr, p_S, NQ, KT, HD, DQ, DQ, KT,
                ZH, NH,
                (long)NQ * DQ, (long)HD,          // A strides (batch, head)
                (long)KT * DQ, (long)HD,          // B strides
                (long)NH * NQ * KT, (long)NQ * KT,// C strides
                0.125f, 0, 0, 0);
    softmax_kernel<<<ZH * NQ, 128>>>();
    // ctx[b, n, h*64+d] = P @ V
    launch_gemm(0, p_S, p_v, nullptr, nullptr, p_ctx, NQ, HD, KT, KT, DQ, DQ,
                ZH, NH,
                (long)NH * NQ * KT, (long)NQ * KT,
                (long)KT * DQ, (long)HD,
                (long)NQ * DQ, (long)HD,
                1.f, 0, 0, 0);

    // out projections
    launch_gemm(1, p_ctx, aow, aob, nullptr, p_t1, ROWS, DQ, DQ, DQ, DQ, DQ,
                1, 1, 0, 0, 0, 0, 0, 0, 1.f, 0, 1, 0);
    launch_gemm(1, p_t1, opw, opb, nullptr, p_t2, ROWS, DQ, DQ, DQ, DQ, DQ,
                1, 1, 0, 0, 0, 0, 0, 0, 1.f, 0, 1, 0);

    // LN(on) + gated residual
    final_kernel<<<ROWS, 128>>>(inst, onw, onb, out);
}

// round 14
// speedup vs baseline: 2.2581x; 1.4528x over previous
#include <cuda_runtime.h>
#include <math.h>

// ---------------- problem constants ----------------
#define BB   2
#define NQ   1220
#define ROWS (BB*NQ)        // 2440
#define DQ   512
#define DKV  256
#define H0   512
#define W0   512
#define HP   128
#define WP   128
#define HWP  (HP*WP)        // 16384
#define KT   512            // selected tokens
#define NH   8
#define HD   64
#define ZH   (BB*NH)        // 16 batch-heads

// ---------------- scratch (device globals; no allocs allowed) ----------------
__device__ float g_bev  [BB*DKV*HWP];
__device__ float g_score[BB*HWP];
__device__ int   g_idx  [BB*KT];
__device__ float g_hid  [BB*KT*DKV];
__device__ float g_tokm [BB*KT*DKV];
__device__ float g_kvln [BB*KT*DKV];
__device__ float g_k    [BB*KT*DQ];
__device__ float g_v    [BB*KT*DQ];
__device__ float g_vt   [BB*DQ*KT];       // V transposed: [b][dq][kt]
__device__ float g_aph  [ROWS*DQ];
__device__ float g_qin  [ROWS*DQ];
__device__ float g_qln  [ROWS*DQ];
__device__ float g_q    [ROWS*DQ];
__device__ float g_gh   [ROWS*DQ];
__device__ float g_gate [ROWS*DQ];
__device__ float g_S    [ZH*NQ*KT];
__device__ float g_ctx  [ROWS*DQ];
__device__ float g_t1   [ROWS*DQ];
__device__ float g_t2   [ROWS*DQ];

// ---------------- 1) avg_pool2d 4x4 ----------------
__global__ void pool_kernel(const float* __restrict__ pts) {
    int i  = blockIdx.x * 256 + threadIdx.x;
    int x  = i & (WP - 1);
    int y  = (i >> 7) & (HP - 1);
    int bc = i >> 14;
    const float* p = pts + ((long)bc * H0 + y * 4) * (long)W0 + x * 4;
    float s = 0.f;
#pragma unroll
    for (int r = 0; r < 4; ++r) {
        float4 v = *(const float4*)(p + (long)r * W0);
        s += v.x + v.y + v.z + v.w;
    }
    g_bev[i] = s * 0.0625f;
}

// ---------------- 2) score = mean_c bev^2 ----------------
__global__ void score_kernel() {
    int i  = blockIdx.x * 256 + threadIdx.x;
    int b  = i >> 14;
    int hw = i & (HWP - 1);
    const float* bv = g_bev + (long)b * DKV * HWP + hw;
    float s = 0.f;
#pragma unroll 4
    for (int c = 0; c < DKV; ++c) {
        float v = bv[(long)c * HWP];
        s = fmaf(v, v, s);
    }
    g_score[i] = s * (1.f / DKV);
}

// ---------------- 3) deterministic top-K ----------------
__global__ void topk_kernel() {
    const int b   = blockIdx.x;
    const int tid = threadIdx.x;                  // 1024 threads, 16 elems each
    const float* sc = g_score + b * HWP;
    unsigned ub[16];
#pragma unroll
    for (int j = 0; j < 16; ++j) ub[j] = __float_as_uint(sc[tid * 16 + j]);

    __shared__ int cnt;
    unsigned thr = 0u;
    for (int bit = 31; bit >= 0; --bit) {
        unsigned cand = thr | (1u << bit);
        if (tid == 0) cnt = 0;
        __syncthreads();
        int local = 0;
#pragma unroll
        for (int j = 0; j < 16; ++j) local += (ub[j] >= cand);
        for (int o = 16; o; o >>= 1) local += __shfl_xor_sync(0xffffffffu, local, o);
        if ((tid & 31) == 0) atomicAdd(&cnt, local);
        __syncthreads();
        if (cnt >= KT) thr = cand;
        __syncthreads();
    }
    __shared__ int sbuf[1024];
    __shared__ int tot;
    int c1 = 0;
#pragma unroll
    for (int j = 0; j < 16; ++j) c1 += (ub[j] > thr);
    sbuf[tid] = c1; __syncthreads();
    for (int off = 1; off < 1024; off <<= 1) {
        int v = (tid >= off) ? sbuf[tid - off] : 0;
        __syncthreads();
        sbuf[tid] += v;
        __syncthreads();
    }
    int start = sbuf[tid] - c1;
    if (tid == 1023) tot = sbuf[1023];
    __syncthreads();
    int m = tot;
#pragma unroll
    for (int j = 0; j < 16; ++j)
        if (ub[j] > thr) g_idx[b * KT + (start++)] = tid * 16 + j;
    __syncthreads();
    int c2 = 0;
#pragma unroll
    for (int j = 0; j < 16; ++j) c2 += (ub[j] == thr);
    sbuf[tid] = c2; __syncthreads();
    for (int off = 1; off < 1024; off <<= 1) {
        int v = (tid >= off) ? sbuf[tid - off] : 0;
        __syncthreads();
        sbuf[tid] += v;
        __syncthreads();
    }
    int s2 = m + sbuf[tid] - c2;
#pragma unroll
    for (int j = 0; j < 16; ++j)
        if (ub[j] == thr) { if (s2 < KT) g_idx[b * KT + s2] = tid * 16 + j; s2++; }
}

// ---------------- 4a) per-token pos-mlp hidden ----------------
__global__ void tokhid_kernel(const float* __restrict__ bw1, const float* __restrict__ bb1) {
    int bk = blockIdx.x;
    int c  = threadIdx.x;                         // 256 threads
    int id = g_idx[bk];
    float px = ((id & 127) + 0.5f) * (1.f / WP);
    float py = ((id >> 7)  + 0.5f) * (1.f / HP);
    g_hid[bk * DKV + c] =
        fmaxf(fmaf(bw1[2 * c], px, fmaf(bw1[2 * c + 1], py, bb1[c])), 0.f);
}

// ---------------- 4b) gather + add mlp-out + LN(tn) ----------------
__global__ void gatherln_kernel(const float* __restrict__ tnw, const float* __restrict__ tnb) {
    int bk = blockIdx.x;
    int b  = bk >> 9;
    int id = g_idx[bk];
    int c  = threadIdx.x;                         // 256 threads
    float val = g_bev[((long)b * DKV + c) * HWP + id] + g_tokm[(long)bk * DKV + c];

    float s = val, sq = val * val;
    for (int o = 16; o; o >>= 1) {
        s  += __shfl_xor_sync(0xffffffffu, s, o);
        sq += __shfl_xor_sync(0xffffffffu, sq, o);
    }
    __shared__ float sa[8], sb[8];
    int w = c >> 5;
    if ((c & 31) == 0) { sa[w] = s; sb[w] = sq; }
    __syncthreads();
    s  = sa[0]+sa[1]+sa[2]+sa[3]+sa[4]+sa[5]+sa[6]+sa[7];
    sq = sb[0]+sb[1]+sb[2]+sb[3]+sb[4]+sb[5]+sb[6]+sb[7];
    float mean = s * (1.f / DKV);
    float var  = sq * (1.f / DKV) - mean * mean;
    float rs   = rsqrtf(var + 1e-5f);
    g_kvln[(long)bk * DKV + c] = (val - mean) * rs * tnw[c] + tnb[c];
}

// ---------------- 5) anchor pos-mlp hidden ----------------
__global__ void aph_kernel(const float* __restrict__ anc,
                           const float* __restrict__ aw1, const float* __restrict__ ab1) {
    int i = blockIdx.x * 256 + threadIdx.x;
    int row = i >> 9, c = i & 511;
    float ax = anc[row * 11 + 0], ay = anc[row * 11 + 1];
    float xr = fminf(fmaxf((ax + 51.2f) * (1.f / 102.4f), 0.f), 1.f);
    float yr = fminf(fmaxf((ay + 51.2f) * (1.f / 102.4f), 0.f), 1.f);
    g_aph[i] = fmaxf(fmaf(aw1[2 * c], xr, fmaf(aw1[2 * c + 1], yr, ab1[c])), 0.f);
}

// ---------------- V transpose: g_v[b*KT+kt][dq] -> g_vt[(b*DQ+dq)*KT+kt] ------
__global__ void vtrans_kernel() {
    __shared__ float t[32][33];
    int b   = blockIdx.z;
    int kt0 = blockIdx.x * 32, dq0 = blockIdx.y * 32;
    int x = threadIdx.x, y = threadIdx.y;         // 32 x 8
#pragma unroll
    for (int j = 0; j < 4; ++j)
        t[y + 8 * j][x] = g_v[((long)b * KT + kt0 + y + 8 * j) * DQ + dq0 + x];
    __syncthreads();
#pragma unroll
    for (int j = 0; j < 4; ++j)
        g_vt[((long)b * DQ + dq0 + y + 8 * j) * KT + kt0 + x] = t[x][y + 8 * j];
}

// ---------------- tf32 helpers ----------------
__device__ __forceinline__ unsigned tf32_of(float f) {
    unsigned u;
    asm("cvt.rna.tf32.f32 %0, %1;" : "=r"(u) : "f"(f));
    return u;
}
__device__ __forceinline__ uint4 f4_tf32(float4 v) {
    uint4 u;
    u.x = tf32_of(v.x); u.y = tf32_of(v.y); u.z = tf32_of(v.z); u.w = tf32_of(v.w);
    return u;
}
__device__ __forceinline__ void mma_tf32(float& c0, float& c1, float& c2, float& c3,
                                         unsigned a0, unsigned a1, unsigned a2, unsigned a3,
                                         unsigned b0, unsigned b1) {
    asm("mma.sync.aligned.m16n8k8.row.col.f32.tf32.tf32.f32 "
        "{%0,%1,%2,%3},{%4,%5,%6,%7},{%8,%9},{%0,%1,%2,%3};"
        : "+f"(c0), "+f"(c1), "+f"(c2), "+f"(c3)
        : "r"(a0), "r"(a1), "r"(a2), "r"(a3), "r"(b0), "r"(b1));
}

// ---------------- tf32 tensor-core GEMM: C = act(alpha * A @ B^T + bias) (+res)
// A: [M,K] row-major (lda). B: [N,K] row-major (ldb). 128x64x16 tile, 256 thr.
// Requires N % 64 == 0, K % 16 == 0, 16B-aligned rows (all call sites satisfy).
#define BM 128
#define BN 64
#define BK 16
#define LDP 20   // padded smem row stride (conflict-free: (20g+t4)%32 all-distinct)
__global__ void __launch_bounds__(256) gemm_tc_kernel(
        const float* __restrict__ A, const float* __restrict__ Bm,
        const float* __restrict__ bias, const float* __restrict__ res,
        float* __restrict__ C,
        int M, int N, int Kd, int lda, int ldb, int ldc,
        int zMod, long aSB, long aSH, long bSB, long bSH,
        long cSB, long cSH,
        float alpha, int act, int hasBias, int hasRes) {
    int z  = blockIdx.z;
    int zb = z / zMod, zh = z % zMod;
    A  += zb * aSB + zh * aSH;
    Bm += zb * bSB + zh * bSH;
    long coff = zb * cSB + zh * cSH;

    const int tid  = threadIdx.x;
    const int lane = tid & 31;
    const int g    = lane >> 2;           // 0..7
    const int t4   = lane & 3;            // 0..3
    const int wid  = tid >> 5;
    const int m0   = (wid & 3) * 32;      // warp M offset (4 warps)
    const int n0   = (wid >> 2) * 32;     // warp N offset (2 warps)
    const int i0 = blockIdx.x * BM, j0 = blockIdx.y * BN;

    __shared__ unsigned As[BM * LDP];
    __shared__ unsigned Ws[BN * LDP];
    float acc[2][4][4] = {};

    // A loader: row ar (0..127), 8 k-cols at ac; B loader: row br (0..63), 4 k at bc
    const int ar = tid >> 1, ac = (tid & 1) * 8;
    const int br = tid >> 2, bc = (tid & 3) * 4;

    float4 ra0, ra1, rb;
    // ---- prologue: tile 0 ----
    {
        if (i0 + ar < M) {
            const float* ap = A + (long)(i0 + ar) * lda + ac;
            ra0 = *(const float4*)ap; ra1 = *(const float4*)(ap + 4);
        } else { ra0 = make_float4(0,0,0,0); ra1 = ra0; }
        rb = *(const float4*)(Bm + (long)(j0 + br) * ldb + bc);
        *(uint4*)&As[ar * LDP + ac]     = f4_tf32(ra0);
        *(uint4*)&As[ar * LDP + ac + 4] = f4_tf32(ra1);
        *(uint4*)&Ws[br * LDP + bc]     = f4_tf32(rb);
    }
    __syncthreads();

    for (int k0 = 0;;) {
        int kn = k0 + BK;
        bool more = kn < Kd;
        if (more) {
            if (i0 + ar < M) {
                const float* ap = A + (long)(i0 + ar) * lda + kn + ac;
                ra0 = *(const float4*)ap; ra1 = *(const float4*)(ap + 4);
            } else { ra0 = make_float4(0,0,0,0); ra1 = ra0; }
            rb = *(const float4*)(Bm + (long)(j0 + br) * ldb + kn + bc);
        }
        // ---- compute: 2 k-steps of 8 ----
#pragma unroll
        for (int ks = 0; ks < BK; ks += 8) {
            unsigned af[2][4];
#pragma unroll
            for (int mf = 0; mf < 2; ++mf) {
                int rbase = (m0 + mf * 16 + g) * LDP + ks + t4;
                af[mf][0] = As[rbase];
                af[mf][1] = As[rbase + 8 * LDP];
                af[mf][2] = As[rbase + 4];
                af[mf][3] = As[rbase + 8 * LDP + 4];
            }
#pragma unroll
            for (int nf = 0; nf < 4; ++nf) {
                int cb = (n0 + nf * 8 + g) * LDP + ks + t4;
                unsigned b0 = Ws[cb], b1 = Ws[cb + 4];
                mma_tf32(acc[0][nf][0], acc[0][nf][1], acc[0][nf][2], acc[0][nf][3],
                         af[0][0], af[0][1], af[0][2], af[0][3], b0, b1);
                mma_tf32(acc[1][nf][0], acc[1][nf][1], acc[1][nf][2], acc[1][nf][3],
                         af[1][0], af[1][1], af[1][2], af[1][3], b0, b1);
            }
        }
        __syncthreads();
        if (!more) break;
        *(uint4*)&As[ar * LDP + ac]     = f4_tf32(ra0);
        *(uint4*)&As[ar * LDP + ac + 4] = f4_tf32(ra1);
        *(uint4*)&Ws[br * LDP + bc]     = f4_tf32(rb);
        __syncthreads();
        k0 = kn;
    }

    // ---- epilogue: c0/c1 -> row g, cols t4*2/t4*2+1; c2/c3 -> row g+8 ----
#pragma unroll
    for (int mf = 0; mf < 2; ++mf) {
#pragma unroll
        for (int rr = 0; rr < 2; ++rr) {
            int row = i0 + m0 + mf * 16 + g + rr * 8;
            if (row >= M) continue;
#pragma unroll
            for (int nf = 0; nf < 4; ++nf) {
                int col = j0 + n0 + nf * 8 + t4 * 2;
                float x0 = alpha * acc[mf][nf][rr * 2 + 0];
                float x1 = alpha * acc[mf][nf][rr * 2 + 1];
                if (hasBias) { x0 += bias[col]; x1 += bias[col + 1]; }
                if (act == 1) { x0 = fmaxf(x0, 0.f); x1 = fmaxf(x1, 0.f); }
                else if (act == 2) {
                    x0 = 1.f / (1.f + expf(-x0));
                    x1 = 1.f / (1.f + expf(-x1));
                }
                if (hasRes) {
                    float2 r = *(const float2*)(res + coff + (long)row * ldc + col);
                    x0 += r.x; x1 += r.y;
                }
                float2 o; o.x = x0; o.y = x1;
                *(float2*)(C + coff + (long)row * ldc + col) = o;
            }
        }
    }
}

// ---------------- LayerNorm over 512 ----------------
__global__ void ln512_kernel(const float* __restrict__ X, const float* __restrict__ w,
                             const float* __restrict__ bb, float* __restrict__ Y) {
    int row = blockIdx.x, t = threadIdx.x;        // 128 threads
    float4 v = *(const float4*)(X + (long)row * DQ + t * 4);
    float s  = v.x + v.y + v.z + v.w;
    float sq = v.x*v.x + v.y*v.y + v.z*v.z + v.w*v.w;
    for (int o = 16; o; o >>= 1) {
        s  += __shfl_xor_sync(0xffffffffu, s, o);
        sq += __shfl_xor_sync(0xffffffffu, sq, o);
    }
    __shared__ float sa[4], sb[4];
    int wp = t >> 5;
    if ((t & 31) == 0) { sa[wp] = s; sb[wp] = sq; }
    __syncthreads();
    s  = sa[0] + sa[1] + sa[2] + sa[3];
    sq = sb[0] + sb[1] + sb[2] + sb[3];
    float mean = s * (1.f / DQ);
    float var  = sq * (1.f / DQ) - mean * mean;
    float rs   = rsqrtf(var + 1e-5f);
    float4 wv = *(const float4*)(w  + t * 4);
    float4 bv = *(const float4*)(bb + t * 4);
    float4 o;
    o.x = (v.x - mean) * rs * wv.x + bv.x;
    o.y = (v.y - mean) * rs * wv.y + bv.y;
    o.z = (v.z - mean) * rs * wv.z + bv.z;
    o.w = (v.w - mean) * rs * wv.w + bv.w;
    *(float4*)(Y + (long)row * DQ + t * 4) = o;
}

// ---------------- softmax over 512 tokens ----------------
__global__ void softmax_kernel() {
    long row = blockIdx.x;
    float* s = g_S + row * KT;
    int t = threadIdx.x;                          // 128 threads
    float4 v = *(const float4*)(s + t * 4);
    float m = fmaxf(fmaxf(v.x, v.y), fmaxf(v.z, v.w));
    for (int o = 16; o; o >>= 1) m = fmaxf(m, __shfl_xor_sync(0xffffffffu, m, o));
    __shared__ float sm[4], ss[4];
    int wp = t >> 5;
    if ((t & 31) == 0) sm[wp] = m;
    __syncthreads();
    m = fmaxf(fmaxf(sm[0], sm[1]), fmaxf(sm[2], sm[3]));
    float4 e;
    e.x = expf(v.x - m); e.y = expf(v.y - m);
    e.z = expf(v.z - m); e.w = expf(v.w - m);
    float su = e.x + e.y + e.z + e.w;
    for (int o = 16; o; o >>= 1) su += __shfl_xor_sync(0xffffffffu, su, o);
    if ((t & 31) == 0) ss[wp] = su;
    __syncthreads();
    su = ss[0] + ss[1] + ss[2] + ss[3];
    float inv = 1.f / su;
    e.x *= inv; e.y *= inv; e.z *= inv; e.w *= inv;
    *(float4*)(s + t * 4) = e;
}

// ---------------- final: LN(on) + gated residual ----------------
__global__ void final_kernel(const float* __restrict__ inst, const float* __restrict__ onw,
                             const float* __restrict__ onb, float* __restrict__ out) {
    int row = blockIdx.x, t = threadIdx.x;        // 128 threads
    float4 v = *(const float4*)(g_t2 + (long)row * DQ + t * 4);
    float s  = v.x + v.y + v.z + v.w;
    float sq = v.x*v.x + v.y*v.y + v.z*v.z + v.w*v.w;
    for (int o = 16; o; o >>= 1) {
        s  += __shfl_xor_sync(0xffffffffu, s, o);
        sq += __shfl_xor_sync(0xffffffffu, sq, o);
    }
    __shared__ float sa[4], sb[4];
    int wp = t >> 5;
    if ((t & 31) == 0) { sa[wp] = s; sb[wp] = sq; }
    __syncthreads();
    s  = sa[0] + sa[1] + sa[2] + sa[3];
    sq = sb[0] + sb[1] + sb[2] + sb[3];
    float mean = s * (1.f / DQ);
    float var  = sq * (1.f / DQ) - mean * mean;
    float rs   = rsqrtf(var + 1e-5f);
    float4 wv = *(const float4*)(onw + t * 4);
    float4 bv = *(const float4*)(onb + t * 4);
    float4 g  = *(const float4*)(g_gate + (long)row * DQ + t * 4);
    float4 in = *(const float4*)(inst   + (long)row * DQ + t * 4);
    float4 o;
    o.x = in.x + g.x * ((v.x - mean) * rs * wv.x + bv.x);
    o.y = in.y + g.y * ((v.y - mean) * rs * wv.y + bv.y);
    o.z = in.z + g.z * ((v.z - mean) * rs * wv.z + bv.z);
    o.w = in.w + g.w * ((v.w - mean) * rs * wv.w + bv.w);
    *(float4*)(out + (long)row * DQ + t * 4) = o;
}

// ---------------- host side ----------------
static inline void launch_gemm(
    const float* A, const float* Bm, const float* bias, const float* res, float* C,
    int M, int N, int Kd, int lda, int ldb, int ldc,
    int Z, int zMod, long aSB, long aSH, long bSB, long bSH, long cSB, long cSH,
    float alpha, int act, int hb, int hr) {
    dim3 grid((M + BM - 1) / BM, N / BN, Z);
    gemm_tc_kernel<<<grid, 256>>>(A, Bm, bias, res, C, M, N, Kd, lda, ldb, ldc,
                                  zMod, aSB, aSH, bSB, bSH, cSB, cSH, alpha, act, hb, hr);
}

extern "C" void kernel_launch(void* const* d_in, const int* in_sizes, int n_in,
                              void* d_out, int out_size) {
    const float* inst = (const float*)d_in[0];
    const float* pts  = (const float*)d_in[1];
    const float* anc  = (const float*)d_in[2];
    const float* qw   = (const float*)d_in[3];
    const float* qb   = (const float*)d_in[4];
    const float* kw   = (const float*)d_in[5];
    const float* kb   = (const float*)d_in[6];
    const float* vw   = (const float*)d_in[7];
    const float* vb   = (const float*)d_in[8];
    const float* aow  = (const float*)d_in[9];
    const float* aob  = (const float*)d_in[10];
    const float* qnw  = (const float*)d_in[11];
    const float* qnb  = (const float*)d_in[12];
    const float* tnw  = (const float*)d_in[13];
    const float* tnb  = (const float*)d_in[14];
    const float* onw  = (const float*)d_in[15];
    const float* onb  = (const float*)d_in[16];
    const float* opw  = (const float*)d_in[17];
    const float* opb  = (const float*)d_in[18];
    const float* bw1  = (const float*)d_in[19];
    const float* bb1  = (const float*)d_in[20];
    const float* bw2  = (const float*)d_in[21];
    const float* bb2  = (const float*)d_in[22];
    const float* aw1  = (const float*)d_in[23];
    const float* ab1  = (const float*)d_in[24];
    const float* aw2  = (const float*)d_in[25];
    const float* ab2  = (const float*)d_in[26];
    const float* gw1  = (const float*)d_in[27];
    const float* gb1  = (const float*)d_in[28];
    const float* gw2  = (const float*)d_in[29];
    const float* gb2  = (const float*)d_in[30];
    float* out = (float*)d_out;

    void* p;
    cudaGetSymbolAddress(&p, g_hid);  float* p_hid  = (float*)p;
    cudaGetSymbolAddress(&p, g_tokm); float* p_tokm = (float*)p;
    cudaGetSymbolAddress(&p, g_aph);  float* p_aph  = (float*)p;
    cudaGetSymbolAddress(&p, g_qin);  float* p_qin  = (float*)p;
    cudaGetSymbolAddress(&p, g_qln);  float* p_qln  = (float*)p;
    cudaGetSymbolAddress(&p, g_q);    float* p_q    = (float*)p;
    cudaGetSymbolAddress(&p, g_gh);   float* p_gh   = (float*)p;
    cudaGetSymbolAddress(&p, g_gate); float* p_gate = (float*)p;
    cudaGetSymbolAddress(&p, g_kvln); float* p_kvln = (float*)p;
    cudaGetSymbolAddress(&p, g_k);    float* p_k    = (float*)p;
    cudaGetSymbolAddress(&p, g_v);    float* p_v    = (float*)p;
    cudaGetSymbolAddress(&p, g_vt);   float* p_vt   = (float*)p;
    cudaGetSymbolAddress(&p, g_S);    float* p_S    = (float*)p;
    cudaGetSymbolAddress(&p, g_ctx);  float* p_ctx  = (float*)p;
    cudaGetSymbolAddress(&p, g_t1);   float* p_t1   = (float*)p;
    cudaGetSymbolAddress(&p, g_t2);   float* p_t2   = (float*)p;

    // BEV pipeline
    pool_kernel <<<(BB * DKV * HWP) / 256, 256>>>(pts);
    score_kernel<<<(BB * HWP) / 256, 256>>>();
    topk_kernel <<<BB, 1024>>>();
    tokhid_kernel<<<BB * KT, 256>>>(bw1, bb1);
    // tokm = hid @ bw2^T + bb2   [1024 x 256 x 256]
    launch_gemm(p_hid, bw2, bb2, nullptr, p_tokm, BB * KT, DKV, DKV, DKV, DKV, DKV,
                1, 1, 0, 0, 0, 0, 0, 0, 1.f, 0, 1, 0);
    gatherln_kernel<<<BB * KT, 256>>>(tnw, tnb);

    // query path
    aph_kernel<<<(ROWS * DQ) / 256, 256>>>(anc, aw1, ab1);
    // qin = aph @ ap_w2^T + ap_b2 + instance
    launch_gemm(p_aph, aw2, ab2, inst, p_qin, ROWS, DQ, DQ, DQ, DQ, DQ,
                1, 1, 0, 0, 0, 0, 0, 0, 1.f, 0, 1, 1);
    ln512_kernel<<<ROWS, 128>>>(p_qin, qnw, qnb, p_qln);
    // q = qln @ qw^T + qb
    launch_gemm(p_qln, qw, qb, nullptr, p_q, ROWS, DQ, DQ, DQ, DQ, DQ,
                1, 1, 0, 0, 0, 0, 0, 0, 1.f, 0, 1, 0);
    // gate hidden = relu(qin @ g_w1^T + g_b1)
    launch_gemm(p_qin, gw1, gb1, nullptr, p_gh, ROWS, DQ, DQ, DQ, DQ, DQ,
                1, 1, 0, 0, 0, 0, 0, 0, 1.f, 1, 1, 0);
    // gate = sigmoid(gh @ g_w2^T + g_b2)
    launch_gemm(p_gh, gw2, gb2, nullptr, p_gate, ROWS, DQ, DQ, DQ, DQ, DQ,
                1, 1, 0, 0, 0, 0, 0, 0, 1.f, 2, 1, 0);

    // k/v projections: [B*K, 256] @ [512,256]^T
    launch_gemm(p_kvln, kw, kb, nullptr, p_k, BB * KT, DQ, DKV, DKV, DKV, DQ,
                1, 1, 0, 0, 0, 0, 0, 0, 1.f, 0, 1, 0);
    launch_gemm(p_kvln, vw, vb, nullptr, p_v, BB * KT, DQ, DKV, DKV, DKV, DQ,
                1, 1, 0, 0, 0, 0, 0, 0, 1.f, 0, 1, 0);
    vtrans_kernel<<<dim3(KT / 32, DQ / 32, BB), dim3(32, 8)>>>();

    // S[b,h] = 0.125 * q_h @ k_h^T   (16 batch-heads)
    launch_gemm(p_q, p_k, nullptr, nullptr, p_S, NQ, KT, HD, DQ, DQ, KT,
                ZH, NH,
                (long)NQ * DQ, (long)HD,
                (long)KT * DQ, (long)HD,
                (long)NH * NQ * KT, (long)NQ * KT,
                0.125f, 0, 0, 0);
    softmax_kernel<<<ZH * NQ, 128>>>();
    // ctx[b, n, h*64+d] = P @ Vt^T  (Vt rows are [dq][kt])
    launch_gemm(p_S, p_vt, nullptr, nullptr, p_ctx, NQ, HD, KT, KT, KT, DQ,
                ZH, NH,
                (long)NH * NQ * KT, (long)NQ * KT,
                (long)DQ * KT, (long)HD * KT,
                (long)NQ * DQ, (long)HD,
                1.f, 0, 0, 0);

    // out projections
    launch_gemm(p_ctx, aow, aob, nullptr, p_t1, ROWS, DQ, DQ, DQ, DQ, DQ,
                1, 1, 0, 0, 0, 0, 0, 0, 1.f, 0, 1, 0);
    launch_gemm(p_t1, opw, opb, nullptr, p_t2, ROWS, DQ, DQ, DQ, DQ, DQ,
                1, 1, 0, 0, 0, 0, 0, 0, 1.f, 0, 1, 0);

    // LN(on) + gated residual
    final_kernel<<<ROWS, 128>>>(inst, onw, onb, out);
}